// round 6
// baseline (speedup 1.0000x reference)
#include <cuda_runtime.h>
#include <cuda_bf16.h>

// Problem constants (fixed by the reference setup)
constexpr int N    = 100000;   // nodes
constexpr int E    = 300000;   // directed edges
constexpr int ETOT = E + N;    // + self loops
constexpr int NG   = 4096;     // graphs
constexpr int HID  = 128;
constexpr int FIN  = 22;

// ---------------- scratch (device globals; no allocations allowed) ----------
__device__ float g_h[N * HID];      // transformed features h = A@W (per layer)
__device__ float g_out[N * HID];    // aggregated messages (per layer)
__device__ float g_als[N * 4];      // per-node src attention logits (H<=4)
__device__ float g_ald[N * 4];      // per-node dst attention logits
__device__ float g_ex[ETOT * 4];    // exp(leaky(e)) per edge per head
__device__ float g_den[N * 4];      // softmax denominators per dst per head
__device__ float g_bnsum[HID];
__device__ float g_bnsq[HID];
__device__ float g_pool[NG * HID];
__device__ float g_cnt[NG];

// ---------------- zero kernels ----------------------------------------------
__global__ void zero_layer_kernel() {
    int i = blockIdx.x * 256 + threadIdx.x;
    if (i < N * HID) g_out[i] = 0.f;
    if (i < N * 4)   g_den[i] = 0.f;
    if (i < HID) { g_bnsum[i] = 0.f; g_bnsq[i] = 0.f; }
}

__global__ void zero_pool_kernel() {
    int i = blockIdx.x * 256 + threadIdx.x;
    if (i < NG * HID) g_pool[i] = 0.f;
    if (i < NG)       g_cnt[i] = 0.f;
}

// ---------------- GEMM + fused attention projections ------------------------
// h = A[N,K] @ W[K,128]; al_s[n,head] = sum_c h[n,head*C+c]*a_s[head,c]
// Block: 128 threads (one per output feature), 4 nodes per block.
// SRC_GH: read input from the device-global g_h (in-kernel symbol reference —
// passing the __device__ symbol from HOST code passes the host shadow address,
// which on GB300/ATS silently reads zeros).
// Safe in-place for g_h: each block reads only its own 4 rows into shared
// before writing them back.
template<int K, int H, bool SRC_GH>
__global__ void gemm_att(const float* __restrict__ Aext, const float* __restrict__ W,
                         const float* __restrict__ a_s, const float* __restrict__ a_d)
{
    constexpr int NPB = 4;
    __shared__ float sA[NPB * K];
    __shared__ float sredS[NPB][4];
    __shared__ float sredD[NPB][4];

    const float* A = SRC_GH ? (const float*)g_h : Aext;

    const int n0 = blockIdx.x * NPB;
    const int f  = threadIdx.x;

    for (int i = f; i < NPB * K; i += 128) {
        int t = i / K, k = i - t * K;
        sA[i] = A[(long)(n0 + t) * K + k];
    }
    __syncthreads();

    float acc[NPB] = {0.f, 0.f, 0.f, 0.f};
#pragma unroll 4
    for (int k = 0; k < K; k++) {
        float w = W[k * HID + f];
#pragma unroll
        for (int t = 0; t < NPB; t++) acc[t] += sA[t * K + k] * w;
    }

    const float as_f = a_s[f];
    const float ad_f = a_d[f];
    const int warp = f >> 5, lane = f & 31;

#pragma unroll
    for (int t = 0; t < NPB; t++) {
        g_h[(long)(n0 + t) * HID + f] = acc[t];
        float vs = acc[t] * as_f;
        float vd = acc[t] * ad_f;
#pragma unroll
        for (int o = 16; o; o >>= 1) {
            vs += __shfl_down_sync(0xFFFFFFFFu, vs, o);
            vd += __shfl_down_sync(0xFFFFFFFFu, vd, o);
        }
        if (lane == 0) { sredS[t][warp] = vs; sredD[t][warp] = vd; }
    }
    __syncthreads();

    if (H == 4) {
        if (f < 16) {
            int t = f >> 2, w = f & 3;
            g_als[(n0 + t) * 4 + w] = sredS[t][w];
            g_ald[(n0 + t) * 4 + w] = sredD[t][w];
        }
    } else { // H == 1
        if (f < NPB) {
            float s = 0.f, d = 0.f;
#pragma unroll
            for (int w = 0; w < 4; w++) { s += sredS[f][w]; d += sredD[f][w]; }
            g_als[n0 + f] = s;
            g_ald[n0 + f] = d;
        }
    }
}

// ---------------- per-edge attention logits + softmax denominators ----------
// segment_max skipped: softmax is shift-invariant; logits are O(1) so exp is safe.
template<int H>
__global__ void edge_att(const int* __restrict__ ei)
{
    int idx = blockIdx.x * 256 + threadIdx.x;
    if (idx >= ETOT * H) return;
    int e = idx / H, hh = idx - e * H;
    int s, d;
    if (e < E) { s = ei[e]; d = ei[E + e]; }
    else       { s = d = e - E; }                // self loop
    float x = g_als[s * H + hh] + g_ald[d * H + hh];
    float l = x > 0.f ? x : 0.2f * x;            // leaky_relu(0.2)
    float ex = expf(l);
    g_ex[idx] = ex;
    atomicAdd(&g_den[d * H + hh], ex);
}

// ---------------- message aggregation: out[dst] += alpha * h[src] -----------
// One thread per (edge, 4 features): float4 gather of h[src], 4 scatter-adds.
template<int H>
__global__ void edge_aggr(const int* __restrict__ ei)
{
    int idx = blockIdx.x * 256 + threadIdx.x;          // ETOT * 32 threads
    if (idx >= ETOT * 32) return;
    int e = idx >> 5, q = idx & 31;                    // q: which float4 (0..31)
    int f = q << 2;                                    // feature base
    int s, d;
    if (e < E) { s = ei[e]; d = ei[E + e]; }
    else       { s = d = e - E; }
    int hh = (H == 4) ? (f >> 5) : 0;
    float alpha = g_ex[e * H + hh] / (g_den[d * H + hh] + 1e-16f);
    float4 hv = *(const float4*)&g_h[(long)s * HID + f];
    float* o = &g_out[(long)d * HID + f];
    atomicAdd(o + 0, hv.x * alpha);
    atomicAdd(o + 1, hv.y * alpha);
    atomicAdd(o + 2, hv.z * alpha);
    atomicAdd(o + 3, hv.w * alpha);
}

// ---------------- BatchNorm stats (two-stage reduction) ---------------------
constexpr int BN_CHUNK = 500;   // 200 blocks * 500 nodes = N
__global__ void bn_stats()
{
    int f  = threadIdx.x;              // 128 threads, one per feature
    int n0 = blockIdx.x * BN_CHUNK;
    float s = 0.f, q = 0.f;
    for (int i = 0; i < BN_CHUNK; i++) {
        float v = g_out[(long)(n0 + i) * HID + f];
        s += v; q += v * v;
    }
    atomicAdd(&g_bnsum[f], s);
    atomicAdd(&g_bnsq[f], q);
}

// Apply BN (+gamma,beta) + ReLU; writes activation into g_h (next layer input).
// Note: the GAT bias b cancels exactly through BN, so it was never added.
__global__ void bn_apply(const float* __restrict__ gma, const float* __restrict__ bta)
{
    int idx = blockIdx.x * 256 + threadIdx.x;
    if (idx >= N * HID) return;
    int f = idx & 127;
    float m   = g_bnsum[f] * (1.0f / N);
    float var = g_bnsq[f] * (1.0f / N) - m * m;
    float y = (g_out[idx] - m) * rsqrtf(var + 1e-5f) * gma[f] + bta[f];
    g_h[idx] = y > 0.f ? y : 0.f;
}

// ---------------- global mean pool ------------------------------------------
__global__ void pool_cnt(const int* __restrict__ batch)
{
    int n = blockIdx.x * 256 + threadIdx.x;
    if (n < N) atomicAdd(&g_cnt[batch[n]], 1.f);
}

__global__ void pool_sum(const int* __restrict__ batch)
{
    int idx = blockIdx.x * 256 + threadIdx.x;
    if (idx >= N * HID) return;
    int n = idx >> 7, f = idx & 127;
    atomicAdd(&g_pool[(long)batch[n] * HID + f], g_h[idx]);
}

// ---------------- MLP head: relu(pooled@fw1+fb1)@fw2+fb2 --------------------
__global__ void mlp_head(const float* __restrict__ fw1, const float* __restrict__ fb1,
                         const float* __restrict__ fw2, const float* __restrict__ fb2,
                         float* __restrict__ out)
{
    __shared__ float ph[HID];
    __shared__ float part[2];
    int g = blockIdx.x, j = threadIdx.x;       // 64 threads
    float c = g_cnt[g];
    float inv = 1.f / (c < 1.f ? 1.f : c);
    ph[j]      = g_pool[g * HID + j] * inv;
    ph[j + 64] = g_pool[g * HID + 64 + j] * inv;
    __syncthreads();

    float acc = fb1[j];
#pragma unroll
    for (int k = 0; k < HID; k++) acc += ph[k] * fw1[k * 64 + j];
    float z = acc > 0.f ? acc : 0.f;
    float p = z * fw2[j];
#pragma unroll
    for (int o = 16; o; o >>= 1) p += __shfl_down_sync(0xFFFFFFFFu, p, o);
    if ((j & 31) == 0) part[j >> 5] = p;
    __syncthreads();
    if (j == 0) out[g] = part[0] + part[1] + fb2[0];
}

// ---------------- host driver ------------------------------------------------
extern "C" void kernel_launch(void* const* d_in, const int* in_sizes, int n_in,
                              void* d_out, int out_size)
{
    const float* x     = (const float*)d_in[0];
    const int*   ei    = (const int*)  d_in[1];
    const int*   batch = (const int*)  d_in[2];
    const float* W1  = (const float*)d_in[3];
    const float* as1 = (const float*)d_in[4];
    const float* ad1 = (const float*)d_in[5];
    const float* g1  = (const float*)d_in[7];
    const float* be1 = (const float*)d_in[8];
    const float* W2  = (const float*)d_in[9];
    const float* as2 = (const float*)d_in[10];
    const float* ad2 = (const float*)d_in[11];
    const float* g2  = (const float*)d_in[13];
    const float* be2 = (const float*)d_in[14];
    const float* W3  = (const float*)d_in[15];
    const float* as3 = (const float*)d_in[16];
    const float* ad3 = (const float*)d_in[17];
    const float* g3  = (const float*)d_in[19];
    const float* be3 = (const float*)d_in[20];
    const float* fw1 = (const float*)d_in[21];
    const float* fb1 = (const float*)d_in[22];
    const float* fw2 = (const float*)d_in[23];
    const float* fb2 = (const float*)d_in[24];
    float* out = (float*)d_out;

    const int ZL_GRID   = (N * HID + 255) / 256;        // 50000
    const int GEMM_GRID = N / 4;                        // 25000
    const int EA4_GRID  = (ETOT * 4 + 255) / 256;
    const int EA1_GRID  = (ETOT * 1 + 255) / 256;
    const int AGG_GRID  = (ETOT * 32 + 255) / 256;      // 50000
    const int BNA_GRID  = (N * HID + 255) / 256;
    const int BNS_GRID  = N / BN_CHUNK;                 // 200

    // ---- Layer 1: 22 -> 4x32  (input from harness buffer x)
    zero_layer_kernel<<<ZL_GRID, 256>>>();
    gemm_att<FIN, 4, false><<<GEMM_GRID, 128>>>(x, W1, as1, ad1);
    edge_att<4><<<EA4_GRID, 256>>>(ei);
    edge_aggr<4><<<AGG_GRID, 256>>>(ei);
    bn_stats<<<BNS_GRID, 128>>>();
    bn_apply<<<BNA_GRID, 256>>>(g1, be1);

    // ---- Layer 2: 128 -> 4x32  (input from g_h via in-kernel symbol)
    zero_layer_kernel<<<ZL_GRID, 256>>>();
    gemm_att<HID, 4, true><<<GEMM_GRID, 128>>>(nullptr, W2, as2, ad2);
    edge_att<4><<<EA4_GRID, 256>>>(ei);
    edge_aggr<4><<<AGG_GRID, 256>>>(ei);
    bn_stats<<<BNS_GRID, 128>>>();
    bn_apply<<<BNA_GRID, 256>>>(g2, be2);

    // ---- Layer 3: 128 -> 1x128
    zero_layer_kernel<<<ZL_GRID, 256>>>();
    gemm_att<HID, 1, true><<<GEMM_GRID, 128>>>(nullptr, W3, as3, ad3);
    edge_att<1><<<EA1_GRID, 256>>>(ei);
    edge_aggr<1><<<AGG_GRID, 256>>>(ei);
    bn_stats<<<BNS_GRID, 128>>>();
    bn_apply<<<BNA_GRID, 256>>>(g3, be3);

    // ---- Pool + MLP head
    zero_pool_kernel<<<(NG * HID + 255) / 256, 256>>>();
    pool_cnt<<<(N + 255) / 256, 256>>>(batch);
    pool_sum<<<(N * HID + 255) / 256, 256>>>(batch);
    mlp_head<<<NG, 64>>>(fw1, fb1, fw2, fb2, out);
}

// round 7
// speedup vs baseline: 1.6251x; 1.6251x over previous
#include <cuda_runtime.h>
#include <cuda_bf16.h>

// Problem constants (fixed by the reference setup)
constexpr int N    = 100000;   // nodes
constexpr int E    = 300000;   // directed edges
constexpr int NG   = 4096;     // graphs
constexpr int HID  = 128;
constexpr int FIN  = 22;

constexpr int NCH   = 400;     // scan chunks
constexpr int CHUNK = 250;     // N / NCH
constexpr int BN_CHUNK = 500;  // 200 blocks * 500 = N
constexpr int BN_BLOCKS = N / BN_CHUNK;

// ---------------- scratch (device globals; no allocations allowed) ----------
__device__ float g_h[N * HID];        // transformed features h = A@W (per layer)
__device__ float g_out[N * HID];      // aggregated messages (per layer)
__device__ float g_als[N * 4];        // per-node src attention logits
__device__ float g_ald[N * 4];        // per-node dst attention logits
__device__ float g_bnsum[HID];
__device__ float g_bnsq[HID];
__device__ float g_bnpart[BN_BLOCKS * 2 * HID];
// CSR (built once per launch, reused by all 3 layers)
__device__ int g_deg[N];
__device__ int g_fill[N];
__device__ int g_cbase[NCH];
__device__ int g_rowp[N + 1];
__device__ int g_csrc[E];

// ======================= CSR construction ====================================
__global__ void csr_zero() {
    int i = blockIdx.x * 256 + threadIdx.x;
    if (i < N) { g_deg[i] = 0; g_fill[i] = 0; }
}

__global__ void csr_deg(const int* __restrict__ ei) {
    int e = blockIdx.x * 256 + threadIdx.x;
    if (e < E) atomicAdd(&g_deg[ei[E + e]], 1);
}

// chunk sums + block-wide scan (1 block, 512 threads)
__global__ void csr_scan() {
    __shared__ int ssum[512];
    int t = threadIdx.x;
    int s = 0;
    if (t < NCH) {
        int base = t * CHUNK;
        for (int i = 0; i < CHUNK; i++) s += g_deg[base + i];
    }
    ssum[t] = s;
    __syncthreads();
    for (int o = 1; o < 512; o <<= 1) {
        int v = (t >= o) ? ssum[t - o] : 0;
        __syncthreads();
        ssum[t] += v;
        __syncthreads();
    }
    if (t < NCH) g_cbase[t] = (t ? ssum[t - 1] : 0);
}

__global__ void csr_rowp() {
    int t = blockIdx.x * 256 + threadIdx.x;
    if (t >= NCH) return;
    int run = g_cbase[t];
    int base = t * CHUNK;
    for (int i = 0; i < CHUNK; i++) {
        g_rowp[base + i] = run;
        run += g_deg[base + i];
    }
    if (t == NCH - 1) g_rowp[N] = run;
}

__global__ void csr_fill(const int* __restrict__ ei) {
    int e = blockIdx.x * 256 + threadIdx.x;
    if (e >= E) return;
    int d = ei[E + e];
    int pos = g_rowp[d] + atomicAdd(&g_fill[d], 1);
    g_csrc[pos] = ei[e];
}

// ======================= GEMM + fused attention projections ==================
// h = A[N,K] @ W[K,128];  al_s[n,h] = sum_c h[n,h*C+c]*a_s[h,c]  (same a_d)
// 128 threads (one per output feature), NPB=8 nodes per block.
// f32x2 packed FMA: node pairs packed into 64-bit accumulators.
// SRC: 0 = external pointer (layer 1 input x); 1 = g_out with fused BN+ReLU
// (BN stats must be in g_bnsum/g_bnsq). Device symbols referenced in-kernel
// (host-side symbol pass reads the ATS host shadow -> zeros).
template<int K, int H, int SRC>
__global__ void gemm_att(const float* __restrict__ Aext, const float* __restrict__ W,
                         const float* __restrict__ a_s, const float* __restrict__ a_d,
                         const float* __restrict__ gma, const float* __restrict__ bta)
{
    constexpr int NPB = 8;
    __shared__ __align__(16) float sA[K][NPB];   // k-major: pairs contiguous
    __shared__ float sredS[NPB][4];
    __shared__ float sredD[NPB][4];

    const int n0 = blockIdx.x * NPB;
    const int f  = threadIdx.x;

    // Stage NPB input rows (transposed), with BN+ReLU fused when SRC==1.
    for (int i = f; i < NPB * K; i += 128) {
        int t = i / K, k = i - t * K;
        float v;
        if (SRC == 0) {
            v = Aext[(n0 + t) * K + k];
        } else {
            float raw = g_out[(n0 + t) * K + k];
            float m   = g_bnsum[k] * (1.0f / N);
            float var = g_bnsq[k] * (1.0f / N) - m * m;
            float y = (raw - m) * rsqrtf(var + 1e-5f) * gma[k] + bta[k];
            v = y > 0.f ? y : 0.f;
        }
        sA[k][t] = v;
    }
    __syncthreads();

    unsigned long long acc[NPB / 2] = {0ull, 0ull, 0ull, 0ull}; // (0.f,0.f) pairs
#pragma unroll 4
    for (int k = 0; k < K; k++) {
        float w = W[k * HID + f];
        unsigned long long ww;
        asm("mov.b64 %0, {%1, %1};" : "=l"(ww) : "r"(__float_as_uint(w)));
        const unsigned long long* ap =
            reinterpret_cast<const unsigned long long*>(&sA[k][0]);
#pragma unroll
        for (int p = 0; p < NPB / 2; p++) {
            asm("fma.rn.f32x2 %0, %1, %2, %0;" : "+l"(acc[p]) : "l"(ap[p]), "l"(ww));
        }
    }

    // Unpack accumulators
    float a[NPB];
#pragma unroll
    for (int p = 0; p < NPB / 2; p++) {
        unsigned int lo, hi;
        asm("mov.b64 {%0, %1}, %2;" : "=r"(lo), "=r"(hi) : "l"(acc[p]));
        a[2 * p]     = __uint_as_float(lo);
        a[2 * p + 1] = __uint_as_float(hi);
    }

    const float as_f = a_s[f];
    const float ad_f = a_d[f];
    const int warp = f >> 5, lane = f & 31;

#pragma unroll
    for (int t = 0; t < NPB; t++) {
        g_h[(n0 + t) * HID + f] = a[t];
        float vs = a[t] * as_f;
        float vd = a[t] * ad_f;
#pragma unroll
        for (int o = 16; o; o >>= 1) {
            vs += __shfl_down_sync(0xFFFFFFFFu, vs, o);
            vd += __shfl_down_sync(0xFFFFFFFFu, vd, o);
        }
        if (lane == 0) { sredS[t][warp] = vs; sredD[t][warp] = vd; }
    }
    __syncthreads();

    if (H == 4) {
        if (f < 32) {
            int t = f >> 2, w = f & 3;
            g_als[(n0 + t) * 4 + w] = sredS[t][w];
            g_ald[(n0 + t) * 4 + w] = sredD[t][w];
        }
    } else { // H == 1
        if (f < NPB) {
            float s = 0.f, d = 0.f;
#pragma unroll
            for (int w = 0; w < 4; w++) { s += sredS[f][w]; d += sredD[f][w]; }
            g_als[n0 + f] = s;
            g_ald[n0 + f] = d;
        }
    }
}

// ======================= Fused attention softmax + aggregation ===============
// One warp per dst node: out[d] = (sum_e ex_e * h[src_e]) / (sum_e ex_e + 1e-16)
// with ex_e = exp(leaky_relu(als[src]+ald[d])). Identical to segment-softmax
// then weighted sum; segment_max skipped (shift-invariant, logits O(1)).
// No atomics, no zeroing, no per-edge buffers.
template<int H>
__global__ void node_aggr()
{
    const int warp = threadIdx.x >> 5, lane = threadIdx.x & 31;
    const int node = blockIdx.x * 8 + warp;
    const int f  = lane << 2;                       // 4 features per lane
    const int hh = (H == 4) ? (lane >> 3) : 0;

    const float ald_d = g_ald[node * H + hh];

    // self loop
    float x = g_als[node * H + hh] + ald_d;
    float l = x > 0.f ? x : 0.2f * x;
    float ex = expf(l);
    float den = ex;
    float4 hv = *(const float4*)&g_h[node * HID + f];
    float4 acc = make_float4(ex * hv.x, ex * hv.y, ex * hv.z, ex * hv.w);

    const int r1 = g_rowp[node + 1];
    for (int k = g_rowp[node]; k < r1; k++) {
        int s = g_csrc[k];
        float xx = g_als[s * H + hh] + ald_d;
        float ll = xx > 0.f ? xx : 0.2f * xx;
        float e2 = expf(ll);
        den += e2;
        float4 h2 = *(const float4*)&g_h[s * HID + f];
        acc.x += e2 * h2.x; acc.y += e2 * h2.y;
        acc.z += e2 * h2.z; acc.w += e2 * h2.w;
    }
    float inv = 1.f / (den + 1e-16f);
    acc.x *= inv; acc.y *= inv; acc.z *= inv; acc.w *= inv;
    *(float4*)&g_out[node * HID + f] = acc;
}

// ======================= BatchNorm stats (partials, no atomics) ==============
__global__ void bn_stats()
{
    int f  = threadIdx.x;              // 128 threads, one per feature
    int n0 = blockIdx.x * BN_CHUNK;
    float s = 0.f, q = 0.f;
    for (int i = 0; i < BN_CHUNK; i++) {
        float v = g_out[(n0 + i) * HID + f];
        s += v; q += v * v;
    }
    g_bnpart[blockIdx.x * (2 * HID) + f]       = s;
    g_bnpart[blockIdx.x * (2 * HID) + HID + f] = q;
}

__global__ void bn_reduce()
{
    int f = threadIdx.x;               // 1 block, 128 threads
    float s = 0.f, q = 0.f;
    for (int b = 0; b < BN_BLOCKS; b++) {
        s += g_bnpart[b * (2 * HID) + f];
        q += g_bnpart[b * (2 * HID) + HID + f];
    }
    g_bnsum[f] = s;
    g_bnsq[f]  = q;
}

// ======================= Pool (BN+ReLU fused) + MLP head =====================
// batch is sorted: block g binary-searches its node range, means BN'd layer-3
// activations, then runs the 128->64->1 MLP. No atomics, no pool buffers.
__device__ __forceinline__ int lowb(const int* b, int v) {
    int lo = 0, hi = N;
    while (lo < hi) { int m = (lo + hi) >> 1; if (b[m] < v) lo = m + 1; else hi = m; }
    return lo;
}

__global__ void pool_mlp(const int* __restrict__ batch,
                         const float* __restrict__ gma, const float* __restrict__ bta,
                         const float* __restrict__ fw1, const float* __restrict__ fb1,
                         const float* __restrict__ fw2, const float* __restrict__ fb2,
                         float* __restrict__ out)
{
    __shared__ float ph[HID];
    __shared__ int srange[2];
    __shared__ float part[2];
    const int g = blockIdx.x, f = threadIdx.x;   // 128 threads

    if (f == 0) srange[0] = lowb(batch, g);
    if (f == 1) srange[1] = lowb(batch, g + 1);
    __syncthreads();
    const int s0 = srange[0], s1 = srange[1];

    // per-feature BN params (layer 3 stats)
    float m   = g_bnsum[f] * (1.0f / N);
    float var = g_bnsq[f] * (1.0f / N) - m * m;
    float rs  = rsqrtf(var + 1e-5f) * gma[f];
    float bt  = bta[f];

    float sum = 0.f;
    for (int n = s0; n < s1; n++) {
        float y = (g_out[n * HID + f] - m) * rs + bt;
        sum += y > 0.f ? y : 0.f;
    }
    float cnt = (float)(s1 - s0);
    ph[f] = sum / (cnt < 1.f ? 1.f : cnt);
    __syncthreads();

    if (f < 64) {
        float acc = fb1[f];
#pragma unroll
        for (int k = 0; k < HID; k++) acc += ph[k] * fw1[k * 64 + f];
        float z = acc > 0.f ? acc : 0.f;
        float p = z * fw2[f];
#pragma unroll
        for (int o = 16; o; o >>= 1) p += __shfl_down_sync(0xFFFFFFFFu, p, o);
        if ((f & 31) == 0) part[f >> 5] = p;
    }
    __syncthreads();
    if (f == 0) out[g] = part[0] + part[1] + fb2[0];
}

// ======================= host driver =========================================
extern "C" void kernel_launch(void* const* d_in, const int* in_sizes, int n_in,
                              void* d_out, int out_size)
{
    const float* x     = (const float*)d_in[0];
    const int*   ei    = (const int*)  d_in[1];
    const int*   batch = (const int*)  d_in[2];
    const float* W1  = (const float*)d_in[3];
    const float* as1 = (const float*)d_in[4];
    const float* ad1 = (const float*)d_in[5];
    const float* g1  = (const float*)d_in[7];
    const float* be1 = (const float*)d_in[8];
    const float* W2  = (const float*)d_in[9];
    const float* as2 = (const float*)d_in[10];
    const float* ad2 = (const float*)d_in[11];
    const float* g2  = (const float*)d_in[13];
    const float* be2 = (const float*)d_in[14];
    const float* W3  = (const float*)d_in[15];
    const float* as3 = (const float*)d_in[16];
    const float* ad3 = (const float*)d_in[17];
    const float* g3  = (const float*)d_in[19];
    const float* be3 = (const float*)d_in[20];
    const float* fw1 = (const float*)d_in[21];
    const float* fb1 = (const float*)d_in[22];
    const float* fw2 = (const float*)d_in[23];
    const float* fb2 = (const float*)d_in[24];
    float* out = (float*)d_out;

    const int CSRZ = (N + 255) / 256;
    const int CSRE = (E + 255) / 256;
    const int GEMM_GRID = N / 8;      // 12500
    const int AGG_GRID  = N / 8;      // 12500 (8 warps/block)

    // ---- Build CSR (dst-sorted adjacency), reused by all 3 layers
    csr_zero<<<CSRZ, 256>>>();
    csr_deg<<<CSRE, 256>>>(ei);
    csr_scan<<<1, 512>>>();
    csr_rowp<<<2, 256>>>();
    csr_fill<<<CSRE, 256>>>(ei);

    // ---- Layer 1: 22 -> 4x32 (input: x)
    gemm_att<FIN, 4, 0><<<GEMM_GRID, 128>>>(x, W1, as1, ad1, nullptr, nullptr);
    node_aggr<4><<<AGG_GRID, 256>>>();
    bn_stats<<<BN_BLOCKS, 128>>>();
    bn_reduce<<<1, 128>>>();

    // ---- Layer 2: 128 -> 4x32 (input: BN+ReLU(g_out) fused into staging)
    gemm_att<HID, 4, 1><<<GEMM_GRID, 128>>>(nullptr, W2, as2, ad2, g1, be1);
    node_aggr<4><<<AGG_GRID, 256>>>();
    bn_stats<<<BN_BLOCKS, 128>>>();
    bn_reduce<<<1, 128>>>();

    // ---- Layer 3: 128 -> 1x128
    gemm_att<HID, 1, 1><<<GEMM_GRID, 128>>>(nullptr, W3, as3, ad3, g2, be2);
    node_aggr<1><<<AGG_GRID, 256>>>();
    bn_stats<<<BN_BLOCKS, 128>>>();
    bn_reduce<<<1, 128>>>();

    // ---- Pool (BN3+ReLU fused) + MLP head
    pool_mlp<<<NG, 128>>>(batch, g3, be3, fw1, fb1, fw2, fb2, out);
}

// round 8
// speedup vs baseline: 1.6923x; 1.0413x over previous
#include <cuda_runtime.h>
#include <cuda_bf16.h>

// Problem constants (fixed by the reference setup)
constexpr int N    = 100000;   // nodes
constexpr int E    = 300000;   // directed edges
constexpr int NG   = 4096;     // graphs
constexpr int HID  = 128;
constexpr int FIN  = 22;

constexpr int NBLK = (N + 255) / 256;    // 391 scan blocks
constexpr int BN_CHUNK  = 100;
constexpr int BN_BLOCKS = N / BN_CHUNK;  // 1000

// ---------------- scratch (device globals; no allocations allowed) ----------
__device__ float g_h[N * HID];        // transformed features h = A@W (per layer)
__device__ float g_out[N * HID];      // aggregated messages (per layer)
__device__ float g_als[N * 4];        // per-node src attention logits
__device__ float g_ald[N * 4];        // per-node dst attention logits
__device__ float g_bnsum[HID];
__device__ float g_bnsq[HID];
__device__ float g_bnpart[BN_BLOCKS * 2 * HID];
// CSR (built once per launch, reused by all 3 layers)
__device__ int g_deg[N];
__device__ int g_fill[N];
__device__ int g_bsum[NBLK];
__device__ int g_bbase[NBLK];
__device__ int g_rowp[N + 1];
__device__ int g_csrc[E];

// ======================= CSR construction (fully parallel scan) ==============
__global__ void csr_zero() {
    int i = blockIdx.x * 256 + threadIdx.x;
    if (i < N) { g_deg[i] = 0; g_fill[i] = 0; }
}

__global__ void csr_deg(const int* __restrict__ ei) {
    int e = blockIdx.x * 256 + threadIdx.x;
    if (e < E) atomicAdd(&g_deg[ei[E + e]], 1);
}

// Level 1: per-block sum of 256 degrees -> g_bsum
__global__ void csr_bsum() {
    __shared__ int sw[8];
    int b = blockIdx.x, t = threadIdx.x;
    int i = b * 256 + t;
    int v = (i < N) ? g_deg[i] : 0;
#pragma unroll
    for (int o = 16; o; o >>= 1) v += __shfl_down_sync(0xFFFFFFFFu, v, o);
    if ((t & 31) == 0) sw[t >> 5] = v;
    __syncthreads();
    if (t == 0) {
        int s = 0;
#pragma unroll
        for (int j = 0; j < 8; j++) s += sw[j];
        g_bsum[b] = s;
    }
}

// Level 2: single-block exclusive scan of NBLK block sums -> g_bbase
__global__ void csr_scan1() {
    __shared__ int ss[512];
    int t = threadIdx.x;
    int s0 = (t < NBLK) ? g_bsum[t] : 0;
    ss[t] = s0;
    __syncthreads();
    for (int o = 1; o < 512; o <<= 1) {
        int v = (t >= o) ? ss[t - o] : 0;
        __syncthreads();
        ss[t] += v;
        __syncthreads();
    }
    if (t < NBLK) g_bbase[t] = ss[t] - s0;
}

// Level 3: per-block inclusive scan (shfl) + base -> g_rowp
__global__ void csr_rowp2() {
    __shared__ int sw[8];
    int b = blockIdx.x, t = threadIdx.x;
    int lane = t & 31, w = t >> 5;
    int i = b * 256 + t;
    int d = (i < N) ? g_deg[i] : 0;
    int v = d;
#pragma unroll
    for (int o = 1; o < 32; o <<= 1) {
        int u = __shfl_up_sync(0xFFFFFFFFu, v, o);
        if (lane >= o) v += u;
    }
    if (lane == 31) sw[w] = v;
    __syncthreads();
    if (t == 0) {
        int r = 0;
#pragma unroll
        for (int j = 0; j < 8; j++) { int x = sw[j]; sw[j] = r; r += x; }
    }
    __syncthreads();
    int base = g_bbase[b] + sw[w];
    if (i < N)      g_rowp[i] = base + v - d;   // exclusive
    if (i == N - 1) g_rowp[N] = base + v;
}

__global__ void csr_fill(const int* __restrict__ ei) {
    int e = blockIdx.x * 256 + threadIdx.x;
    if (e >= E) return;
    int d = ei[E + e];
    int pos = g_rowp[d] + atomicAdd(&g_fill[d], 1);
    g_csrc[pos] = ei[e];
}

// ======================= GEMM + fused attention projections ==================
// h = A[N,K] @ W[K,128];  al_s[n,h] = sum_c h[n,h*C+c]*a_s[h,c]  (same a_d)
// 128 threads (one per output feature), NPB=16 nodes per block.
// f32x2 packed FMA; node pairs in 64-bit accumulators; k-major smem staging
// read with 16B vector loads. SRC: 0 = external pointer (layer-1 x);
// 1 = g_out with fused BN+ReLU (stats in g_bnsum/g_bnsq). Device symbols are
// referenced IN-KERNEL only (host-side symbol pass = ATS host shadow = zeros).
template<int K, int H, int SRC>
__global__ void gemm_att(const float* __restrict__ Aext, const float* __restrict__ W,
                         const float* __restrict__ a_s, const float* __restrict__ a_d,
                         const float* __restrict__ gma, const float* __restrict__ bta)
{
    constexpr int NPB = 16;
    __shared__ __align__(16) float sA[K][NPB];   // k-major: node pairs contiguous
    __shared__ float sredS[NPB][4];
    __shared__ float sredD[NPB][4];

    const int n0 = blockIdx.x * NPB;
    const int f  = threadIdx.x;

    // Stage NPB input rows (transposed), BN+ReLU fused when SRC==1.
    for (int i = f; i < NPB * K; i += 128) {
        int t = i / K, k = i - t * K;
        float v;
        if (SRC == 0) {
            v = Aext[(n0 + t) * K + k];
        } else {
            float raw = g_out[(n0 + t) * K + k];
            float m   = g_bnsum[k] * (1.0f / N);
            float var = g_bnsq[k] * (1.0f / N) - m * m;
            float y = (raw - m) * rsqrtf(var + 1e-5f) * gma[k] + bta[k];
            v = y > 0.f ? y : 0.f;
        }
        sA[k][t] = v;
    }
    __syncthreads();

    unsigned long long acc[NPB / 2];
#pragma unroll
    for (int p = 0; p < NPB / 2; p++) acc[p] = 0ull;

#pragma unroll 4
    for (int k = 0; k < K; k++) {
        float w = W[k * HID + f];
        unsigned long long ww;
        asm("mov.b64 %0, {%1, %1};" : "=l"(ww) : "r"(__float_as_uint(w)));
        const ulonglong2* ap = reinterpret_cast<const ulonglong2*>(&sA[k][0]);
#pragma unroll
        for (int q = 0; q < NPB / 4; q++) {
            ulonglong2 a2 = ap[q];                 // 16B vector load (4 nodes)
            asm("fma.rn.f32x2 %0, %1, %2, %0;" : "+l"(acc[2*q])   : "l"(a2.x), "l"(ww));
            asm("fma.rn.f32x2 %0, %1, %2, %0;" : "+l"(acc[2*q+1]) : "l"(a2.y), "l"(ww));
        }
    }

    // Unpack accumulators
    float a[NPB];
#pragma unroll
    for (int p = 0; p < NPB / 2; p++) {
        unsigned int lo, hi;
        asm("mov.b64 {%0, %1}, %2;" : "=r"(lo), "=r"(hi) : "l"(acc[p]));
        a[2 * p]     = __uint_as_float(lo);
        a[2 * p + 1] = __uint_as_float(hi);
    }

    const float as_f = a_s[f];
    const float ad_f = a_d[f];
    const int warp = f >> 5, lane = f & 31;

#pragma unroll
    for (int t = 0; t < NPB; t++) {
        g_h[(n0 + t) * HID + f] = a[t];
        float vs = a[t] * as_f;
        float vd = a[t] * ad_f;
#pragma unroll
        for (int o = 16; o; o >>= 1) {
            vs += __shfl_down_sync(0xFFFFFFFFu, vs, o);
            vd += __shfl_down_sync(0xFFFFFFFFu, vd, o);
        }
        if (lane == 0) { sredS[t][warp] = vs; sredD[t][warp] = vd; }
    }
    __syncthreads();

    if (H == 4) {
        if (f < 64) {
            int t = f >> 2, w = f & 3;
            g_als[(n0 + t) * 4 + w] = sredS[t][w];
            g_ald[(n0 + t) * 4 + w] = sredD[t][w];
        }
    } else { // H == 1
        if (f < NPB) {
            float s = 0.f, d = 0.f;
#pragma unroll
            for (int w = 0; w < 4; w++) { s += sredS[f][w]; d += sredD[f][w]; }
            g_als[n0 + f] = s;
            g_ald[n0 + f] = d;
        }
    }
}

// ======================= Fused attention softmax + aggregation ===============
// One warp per dst node: out[d] = (sum_e ex_e * h[src_e]) / (sum_e ex_e + 1e-16)
// with ex_e = exp(leaky_relu(als[src]+ald[d])). Segment_max skipped
// (shift-invariant; logits O(1)). No atomics, no zeroing, no per-edge buffers.
template<int H>
__global__ void node_aggr()
{
    const int warp = threadIdx.x >> 5, lane = threadIdx.x & 31;
    const int node = blockIdx.x * 8 + warp;
    const int f  = lane << 2;                       // 4 features per lane
    const int hh = (H == 4) ? (lane >> 3) : 0;

    const float ald_d = g_ald[node * H + hh];

    // self loop
    float x = g_als[node * H + hh] + ald_d;
    float l = x > 0.f ? x : 0.2f * x;
    float ex = expf(l);
    float den = ex;
    float4 hv = *(const float4*)&g_h[node * HID + f];
    float4 acc = make_float4(ex * hv.x, ex * hv.y, ex * hv.z, ex * hv.w);

    const int r1 = g_rowp[node + 1];
    for (int k = g_rowp[node]; k < r1; k++) {
        int s = g_csrc[k];
        float xx = g_als[s * H + hh] + ald_d;
        float ll = xx > 0.f ? xx : 0.2f * xx;
        float e2 = expf(ll);
        den += e2;
        float4 h2 = *(const float4*)&g_h[s * HID + f];
        acc.x += e2 * h2.x; acc.y += e2 * h2.y;
        acc.z += e2 * h2.z; acc.w += e2 * h2.w;
    }
    float inv = 1.f / (den + 1e-16f);
    acc.x *= inv; acc.y *= inv; acc.z *= inv; acc.w *= inv;
    *(float4*)&g_out[node * HID + f] = acc;
}

// ======================= BatchNorm stats (partials, no atomics) ==============
__global__ void bn_stats()
{
    int f  = threadIdx.x;              // 128 threads, one per feature
    int n0 = blockIdx.x * BN_CHUNK;
    float s = 0.f, q = 0.f;
    for (int i = 0; i < BN_CHUNK; i++) {
        float v = g_out[(n0 + i) * HID + f];
        s += v; q += v * v;
    }
    g_bnpart[blockIdx.x * (2 * HID) + f]       = s;
    g_bnpart[blockIdx.x * (2 * HID) + HID + f] = q;
}

// 4 blocks x 1024 threads: one warp per feature, strided loads + warp reduce.
__global__ void bn_reduce()
{
    int warp = (blockIdx.x * 32) + (threadIdx.x >> 5);  // feature 0..127
    int lane = threadIdx.x & 31;
    float s = 0.f, q = 0.f;
    for (int b = lane; b < BN_BLOCKS; b += 32) {
        s += g_bnpart[b * (2 * HID) + warp];
        q += g_bnpart[b * (2 * HID) + HID + warp];
    }
#pragma unroll
    for (int o = 16; o; o >>= 1) {
        s += __shfl_down_sync(0xFFFFFFFFu, s, o);
        q += __shfl_down_sync(0xFFFFFFFFu, q, o);
    }
    if (lane == 0) { g_bnsum[warp] = s; g_bnsq[warp] = q; }
}

// ======================= Pool (BN+ReLU fused) + MLP head =====================
__device__ __forceinline__ int lowb(const int* b, int v) {
    int lo = 0, hi = N;
    while (lo < hi) { int m = (lo + hi) >> 1; if (b[m] < v) lo = m + 1; else hi = m; }
    return lo;
}

__global__ void pool_mlp(const int* __restrict__ batch,
                         const float* __restrict__ gma, const float* __restrict__ bta,
                         const float* __restrict__ fw1, const float* __restrict__ fb1,
                         const float* __restrict__ fw2, const float* __restrict__ fb2,
                         float* __restrict__ out)
{
    __shared__ float ph[HID];
    __shared__ int srange[2];
    __shared__ float part[2];
    const int g = blockIdx.x, f = threadIdx.x;   // 128 threads

    if (f == 0) srange[0] = lowb(batch, g);
    if (f == 1) srange[1] = lowb(batch, g + 1);
    __syncthreads();
    const int s0 = srange[0], s1 = srange[1];

    float m   = g_bnsum[f] * (1.0f / N);
    float var = g_bnsq[f] * (1.0f / N) - m * m;
    float rs  = rsqrtf(var + 1e-5f) * gma[f];
    float bt  = bta[f];

    float sum = 0.f;
    for (int n = s0; n < s1; n++) {
        float y = (g_out[n * HID + f] - m) * rs + bt;
        sum += y > 0.f ? y : 0.f;
    }
    float cnt = (float)(s1 - s0);
    ph[f] = sum / (cnt < 1.f ? 1.f : cnt);
    __syncthreads();

    if (f < 64) {
        float acc = fb1[f];
#pragma unroll
        for (int k = 0; k < HID; k++) acc += ph[k] * fw1[k * 64 + f];
        float z = acc > 0.f ? acc : 0.f;
        float p = z * fw2[f];
#pragma unroll
        for (int o = 16; o; o >>= 1) p += __shfl_down_sync(0xFFFFFFFFu, p, o);
        if ((f & 31) == 0) part[f >> 5] = p;
    }
    __syncthreads();
    if (f == 0) out[g] = part[0] + part[1] + fb2[0];
}

// ======================= host driver =========================================
extern "C" void kernel_launch(void* const* d_in, const int* in_sizes, int n_in,
                              void* d_out, int out_size)
{
    const float* x     = (const float*)d_in[0];
    const int*   ei    = (const int*)  d_in[1];
    const int*   batch = (const int*)  d_in[2];
    const float* W1  = (const float*)d_in[3];
    const float* as1 = (const float*)d_in[4];
    const float* ad1 = (const float*)d_in[5];
    const float* g1  = (const float*)d_in[7];
    const float* be1 = (const float*)d_in[8];
    const float* W2  = (const float*)d_in[9];
    const float* as2 = (const float*)d_in[10];
    const float* ad2 = (const float*)d_in[11];
    const float* g2  = (const float*)d_in[13];
    const float* be2 = (const float*)d_in[14];
    const float* W3  = (const float*)d_in[15];
    const float* as3 = (const float*)d_in[16];
    const float* ad3 = (const float*)d_in[17];
    const float* g3  = (const float*)d_in[19];
    const float* be3 = (const float*)d_in[20];
    const float* fw1 = (const float*)d_in[21];
    const float* fb1 = (const float*)d_in[22];
    const float* fw2 = (const float*)d_in[23];
    const float* fb2 = (const float*)d_in[24];
    float* out = (float*)d_out;

    const int CSRE = (E + 255) / 256;
    const int GEMM_GRID = N / 16;     // 6250
    const int AGG_GRID  = N / 8;      // 12500 (8 warps/block)

    // ---- Build CSR (dst-sorted adjacency), reused by all 3 layers
    csr_zero<<<NBLK, 256>>>();
    csr_deg<<<CSRE, 256>>>(ei);
    csr_bsum<<<NBLK, 256>>>();
    csr_scan1<<<1, 512>>>();
    csr_rowp2<<<NBLK, 256>>>();
    csr_fill<<<CSRE, 256>>>(ei);

    // ---- Layer 1: 22 -> 4x32 (input: x)
    gemm_att<FIN, 4, 0><<<GEMM_GRID, 128>>>(x, W1, as1, ad1, nullptr, nullptr);
    node_aggr<4><<<AGG_GRID, 256>>>();
    bn_stats<<<BN_BLOCKS, 128>>>();
    bn_reduce<<<4, 1024>>>();

    // ---- Layer 2: 128 -> 4x32 (input: BN+ReLU(g_out) fused into staging)
    gemm_att<HID, 4, 1><<<GEMM_GRID, 128>>>(nullptr, W2, as2, ad2, g1, be1);
    node_aggr<4><<<AGG_GRID, 256>>>();
    bn_stats<<<BN_BLOCKS, 128>>>();
    bn_reduce<<<4, 1024>>>();

    // ---- Layer 3: 128 -> 1x128
    gemm_att<HID, 1, 1><<<GEMM_GRID, 128>>>(nullptr, W3, as3, ad3, g2, be2);
    node_aggr<1><<<AGG_GRID, 256>>>();
    bn_stats<<<BN_BLOCKS, 128>>>();
    bn_reduce<<<4, 1024>>>();

    // ---- Pool (BN3+ReLU fused) + MLP head
    pool_mlp<<<NG, 128>>>(batch, g3, be3, fw1, fb1, fw2, fb2, out);
}